// round 2
// baseline (speedup 1.0000x reference)
#include <cuda_runtime.h>
#include <cstdint>
#include <cstddef>

// ---------------------------------------------------------------------------
// 50-layer LSTM, persistent wavefront kernel, tf32 mma.sync.
//   B=64, T=256, D=H=256, L=50, O=2
// Layout choices:
//   g_h[l][t+1][b][h]   : layer outputs, slot 0 is h_{-1}=0
//   g_wfrag             : weights pre-swizzled into mma B-fragment order,
//                         columns permuted n_local = 4*unit + gate
//   progress flags      : st.release / ld.acquire, one per (layer, cta)
// ---------------------------------------------------------------------------

#define LAYERS 50
#define BATCH  64
#define TSTEPS 256
#define HID    256
#define GPL    2                 // CTAs per layer
#define NCTA   (LAYERS*GPL)      // 100 persistent CTAs (<=148 SMs -> coresident)

// per-(l,cta,wn) fragment block: 64 ktiles * 16 ntiles * 64 floats
#define WFRAG_PER_WARP (64*16*64)
#define HSLOT (BATCH*HID)                    // 16384 floats per time slot
#define HLAYER ((size_t)(TSTEPS+1)*HSLOT)    // 257 slots per layer

__device__ float    g_h[(size_t)LAYERS*HLAYER];                    // ~843 MB
__device__ float    g_wfrag[(size_t)LAYERS*2*4*WFRAG_PER_WARP];    // ~105 MB
__device__ float    g_bias[LAYERS*1024];
__device__ unsigned g_prog[128];

// ------------------------------- helpers -----------------------------------

__device__ __forceinline__ uint32_t f2tf32(float f) {
    uint32_t u;
    asm("cvt.rna.tf32.f32 %0, %1;" : "=r"(u) : "f"(f));
    return u;
}
__device__ __forceinline__ unsigned ld_acq(const unsigned* p) {
    unsigned v;
    asm volatile("ld.acquire.gpu.u32 %0, [%1];" : "=r"(v) : "l"(p) : "memory");
    return v;
}
__device__ __forceinline__ void st_rel(unsigned* p, unsigned v) {
    asm volatile("st.release.gpu.u32 [%0], %1;" :: "l"(p), "r"(v) : "memory");
}
__device__ __forceinline__ void mma8(float acc[4], const uint32_t a[4],
                                     uint32_t b0, uint32_t b1) {
    asm("mma.sync.aligned.m16n8k8.row.col.f32.tf32.tf32.f32 "
        "{%0,%1,%2,%3},{%4,%5,%6,%7},{%8,%9},{%0,%1,%2,%3};"
        : "+f"(acc[0]), "+f"(acc[1]), "+f"(acc[2]), "+f"(acc[3])
        : "r"(a[0]), "r"(a[1]), "r"(a[2]), "r"(a[3]), "r"(b0), "r"(b1));
}
__device__ __forceinline__ float sigm(float x) {
    return __fdividef(1.f, 1.f + __expf(-x));
}
__device__ __forceinline__ float tanh_f(float x) {
    float ax = fabsf(x);
    float e  = __expf(-2.f * ax);
    float r  = __fdividef(1.f - e, 1.f + e);
    return copysignf(r, x);
}

// ------------------------------ prep kernels --------------------------------

// Swizzle W_ih|W_hh into mma B-fragment order, pre-rounded to tf32.
// Linear index decomposition: [l][g][wn][ktile][ntile][e(64)], e=(thread,j).
__global__ void prep_wfrag(const float* __restrict__ Wih,
                           const float* __restrict__ Whh) {
    size_t idx = (size_t)blockIdx.x * 256 + threadIdx.x;
    int e     = (int)(idx & 63);
    int ntile = (int)((idx >> 6)  & 15);
    int ktile = (int)((idx >> 10) & 63);
    int wn    = (int)((idx >> 16) & 3);
    int gg    = (int)((idx >> 18) & 1);
    int l     = (int)(idx >> 19);
    if (l >= LAYERS) return;
    int th = e >> 1, j = e & 1;
    int col  = th >> 2;
    int krow = (th & 3) + j * 4;
    int nloc = wn * 128 + ntile * 8 + col;   // column within CTA's 512
    int u    = nloc >> 2;                    // hidden-unit (0..127)
    int gate = nloc & 3;                     // i,f,g,o
    int r    = gate * 256 + gg * 128 + u;    // original row in [4H]
    int k    = ktile * 8 + krow;             // 0..511 : [x | h]
    float v = (k < 256) ? Wih[((size_t)l * 1024 + r) * 256 + k]
                        : Whh[((size_t)l * 1024 + r) * 256 + (k - 256)];
    g_wfrag[idx] = __uint_as_float(f2tf32(v));
}

__global__ void prep_bias_init(const float* __restrict__ bih,
                               const float* __restrict__ bhh) {
    int idx = blockIdx.x * 256 + threadIdx.x;
    if (idx < LAYERS * 1024) {
        int l = idx >> 10;
        int nl = idx & 1023;
        int gg = nl >> 9;
        int nloc = nl & 511;
        int u = nloc >> 2, gate = nloc & 3;
        int r = gate * 256 + gg * 128 + u;
        g_bias[idx] = bih[l * 1024 + r] + bhh[l * 1024 + r];
    }
    if (idx < 128) g_prog[idx] = 0;
}

__global__ void zero_h0() {
    float* p = g_h + (size_t)blockIdx.x * HLAYER;   // slot 0 = h_{-1}
    for (int i = threadIdx.x; i < HSLOT; i += 256) p[i] = 0.f;
}

// --------------------------- persistent LSTM --------------------------------

__global__ void __launch_bounds__(256, 1)
lstm_persistent(const float* __restrict__ x) {
    const int l   = blockIdx.x / GPL;
    const int gg  = blockIdx.x % GPL;
    const int tid = threadIdx.x;
    const int lane = tid & 31;
    const int warp = tid >> 5;
    const int wm = warp >> 2;        // 0..1 : M half
    const int wn = warp & 3;         // 0..3 : 32-unit group

    __shared__ float cbuf[64 * 130];  // c-state, padded stride (conflict-free)
    __shared__ float sbias[512];

    for (int i = tid; i < 512; i += 256)
        sbias[i] = g_bias[(l * GPL + gg) * 512 + i];
    for (int i = tid; i < 64 * 130; i += 256) cbuf[i] = 0.f;
    __syncthreads();

    const float2* wbase2 = (const float2*)(g_wfrag +
        (size_t)((l * GPL + gg) * 4 + wn) * WFRAG_PER_WARP);
    float* hlayer = g_h + (size_t)l * HLAYER;
    const float* xlayer = (l == 0) ? x : (g_h + (size_t)(l - 1) * HLAYER);
    const size_t xrs = (l == 0) ? (size_t)TSTEPS * 256 : 256;  // row stride

    const int r0 = wm * 32 + (lane >> 2);
    const int q  = lane & 3;

    float acc[2][16][4];

    for (int t = 0; t < TSTEPS; ++t) {
        // ---- wait for dependencies ----
        if (tid == 0) {
            if (l > 0) {
                const unsigned need = (unsigned)(t + 1);
                while (ld_acq(&g_prog[(l - 1) * GPL]) < need ||
                       ld_acq(&g_prog[(l - 1) * GPL + 1]) < need)
                    __nanosleep(64);
            }
            if (t > 0) {
                while (ld_acq(&g_prog[l * GPL + (gg ^ 1)]) < (unsigned)t)
                    __nanosleep(64);
            }
        }
        __syncthreads();

        // xp points at x_t of this layer; hp at h_{t-1}
        const float* xp = (l == 0) ? (x + (size_t)t * 256)
                                   : (xlayer + (size_t)(t + 1) * HSLOT);
        const float* hp = hlayer + (size_t)t * HSLOT;

        // ---- init accumulators with bias ----
        #pragma unroll
        for (int j = 0; j < 16; ++j) {
            float b0 = sbias[wn * 128 + j * 8 + q * 2];
            float b1 = sbias[wn * 128 + j * 8 + q * 2 + 1];
            acc[0][j][0] = b0; acc[0][j][1] = b1; acc[0][j][2] = b0; acc[0][j][3] = b1;
            acc[1][j][0] = b0; acc[1][j][1] = b1; acc[1][j][2] = b0; acc[1][j][3] = b1;
        }

        // ---- GEMM: gates += [x_t | h_{t-1}] @ Wc^T  (K = 512, tf32 mma) ----
        #pragma unroll 1
        for (int ktile = 0; ktile < 64; ++ktile) {
            const int kk = (ktile << 3) + q;
            const float* s;
            size_t rs;
            int ko;
            if (kk < 256) { s = xp; rs = xrs; ko = kk; }
            else          { s = hp; rs = 256; ko = kk - 256; }
            uint32_t A0[4], A1[4];
            A0[0] = f2tf32(__ldg(s + (size_t)(r0     ) * rs + ko));
            A0[1] = f2tf32(__ldg(s + (size_t)(r0 +  8) * rs + ko));
            A0[2] = f2tf32(__ldg(s + (size_t)(r0     ) * rs + ko + 4));
            A0[3] = f2tf32(__ldg(s + (size_t)(r0 +  8) * rs + ko + 4));
            A1[0] = f2tf32(__ldg(s + (size_t)(r0 + 16) * rs + ko));
            A1[1] = f2tf32(__ldg(s + (size_t)(r0 + 24) * rs + ko));
            A1[2] = f2tf32(__ldg(s + (size_t)(r0 + 16) * rs + ko + 4));
            A1[3] = f2tf32(__ldg(s + (size_t)(r0 + 24) * rs + ko + 4));

            const float2* wk = wbase2 + (size_t)ktile * 512 + lane;
            #pragma unroll
            for (int j = 0; j < 16; ++j) {
                float2 bv = __ldg(wk + j * 32);
                uint32_t b0 = __float_as_uint(bv.x);
                uint32_t b1 = __float_as_uint(bv.y);
                mma8(acc[0][j], A0, b0, b1);
                mma8(acc[1][j], A1, b0, b1);
            }
        }

        // ---- elementwise LSTM update ----
        // Column permutation means each thread quad holds (i,f)/(g,o) pairs of
        // one unit; one shfl_xor(1) completes the gate set.
        float* hout = hlayer + (size_t)(t + 1) * HSLOT;
        #pragma unroll
        for (int mt = 0; mt < 2; ++mt) {
            #pragma unroll
            for (int j = 0; j < 16; ++j) {
                float a0 = acc[mt][j][0], a1 = acc[mt][j][1];
                float a2 = acc[mt][j][2], a3 = acc[mt][j][3];
                float p0 = __shfl_xor_sync(0xffffffffu, a0, 1);
                float p1 = __shfl_xor_sync(0xffffffffu, a1, 1);
                float p2 = __shfl_xor_sync(0xffffffffu, a2, 1);
                float p3 = __shfl_xor_sync(0xffffffffu, a3, 1);
                if (!(lane & 1)) {            // even lanes hold (i,f); partner (g,o)
                    int u   = wn * 32 + j * 2 + (q >> 1);
                    int row = wm * 32 + mt * 16 + (lane >> 2);
                    int hcol = gg * 128 + u;
                    {
                        float i_ = sigm(a0), f_ = sigm(a1);
                        float g_ = tanh_f(p0), o_ = sigm(p1);
                        float c  = cbuf[row * 130 + u];
                        float cn = fmaf(f_, c, i_ * g_);
                        cbuf[row * 130 + u] = cn;
                        hout[row * HID + hcol] = o_ * tanh_f(cn);
                    }
                    {
                        int row2 = row + 8;
                        float i_ = sigm(a2), f_ = sigm(a3);
                        float g_ = tanh_f(p2), o_ = sigm(p3);
                        float c  = cbuf[row2 * 130 + u];
                        float cn = fmaf(f_, c, i_ * g_);
                        cbuf[row2 * 130 + u] = cn;
                        hout[row2 * HID + hcol] = o_ * tanh_f(cn);
                    }
                }
            }
        }

        __threadfence();
        __syncthreads();
        if (tid == 0) st_rel(&g_prog[l * GPL + gg], (unsigned)(t + 1));
    }
}

// ------------------------------ output head ---------------------------------

__global__ void out_proj(const float* __restrict__ Wout,
                         const float* __restrict__ bout,
                         float* __restrict__ out) {
    int p = blockIdx.x * 8 + (threadIdx.x >> 5);   // (t*64+b), 16384 total
    int lane = threadIdx.x & 31;
    int t = p >> 6, b = p & 63;
    const float* h = g_h + (size_t)(LAYERS - 1) * HLAYER +
                     (size_t)(t + 1) * HSLOT + (size_t)b * HID;
    const float4* h4 = (const float4*)(h + lane * 8);
    const float4* w0 = (const float4*)(Wout + lane * 8);
    const float4* w1 = (const float4*)(Wout + 256 + lane * 8);
    float4 hv0 = h4[0], hv1 = h4[1];
    float4 a = w0[0], b4 = w0[1], c = w1[0], d = w1[1];
    float s0 = hv0.x*a.x + hv0.y*a.y + hv0.z*a.z + hv0.w*a.w
             + hv1.x*b4.x + hv1.y*b4.y + hv1.z*b4.z + hv1.w*b4.w;
    float s1 = hv0.x*c.x + hv0.y*c.y + hv0.z*c.z + hv0.w*c.w
             + hv1.x*d.x + hv1.y*d.y + hv1.z*d.z + hv1.w*d.w;
    #pragma unroll
    for (int off = 16; off > 0; off >>= 1) {
        s0 += __shfl_xor_sync(0xffffffffu, s0, off);
        s1 += __shfl_xor_sync(0xffffffffu, s1, off);
    }
    if (lane == 0) {
        out[(size_t)b * (TSTEPS * 2) + t * 2 + 0] = sigm(s0 + bout[0]);
        out[(size_t)b * (TSTEPS * 2) + t * 2 + 1] = sigm(s1 + bout[1]);
    }
}

// ------------------------------- launcher -----------------------------------

extern "C" void kernel_launch(void* const* d_in, const int* in_sizes, int n_in,
                              void* d_out, int out_size) {
    const float* x    = (const float*)d_in[0];
    const float* Wih  = (const float*)d_in[1];
    const float* Whh  = (const float*)d_in[2];
    const float* bih  = (const float*)d_in[3];
    const float* bhh  = (const float*)d_in[4];
    const float* Wout = (const float*)d_in[5];
    const float* bout = (const float*)d_in[6];
    float* out = (float*)d_out;

    prep_wfrag<<<102400, 256>>>(Wih, Whh);      // 26.2M fragment elements
    prep_bias_init<<<200, 256>>>(bih, bhh);     // bias permute + progress reset
    zero_h0<<<LAYERS, 256>>>();                 // h_{-1} = 0 slots
    lstm_persistent<<<NCTA, 256>>>(x);          // 100 coresident CTAs
    out_proj<<<2048, 256>>>(Wout, bout, out);   // final sigmoid head
}